// round 17
// baseline (speedup 1.0000x reference)
#include <cuda_runtime.h>
#include <cuda_bf16.h>
#include <cstdint>

#define NT 512
#define VB 128
#define TS 24

// layers 0-2 activations as bf16 A-frag tiles: [t][blk][1024 x uint4] = 50 MB
__device__ uint4 g_actb[TS * 128 * 1024];
// layer-3 h at t=len-1 / t=len-4 only, [j][v_global] = 4 MB each
__device__ float g_sel1[64 * 16384];
__device__ float g_sel2[64 * 16384];

// ---- smem float offsets ----
// weights: L0 WH @0 (6144); L1 WH@6144 WI@12288; L2 WH@18432 WI@24576; L3 WH@30720 WI@36864
#define S_H0  43008   // 4096 u32: h A-frags buf0 (regions disjoint per mg-group)
#define S_H1  47104
#define S_BS  51200   // 4 x 256 fused biases
#define S_W0  52224   // 192 layer-0 rank-1 ih weights
#define S_VIN 52416   // 3072 vin[t][v]
#define SMEM_FLOATS 55488   // 221,952 B

static __device__ __forceinline__ uint32_t pkbf(float lo, float hi) {
    __nv_bfloat162 b = __float22bfloat162_rn(make_float2(lo, hi));
    return *(uint32_t*)&b;
}
static __device__ __forceinline__ float tanha(float x) {
    float y; asm("tanh.approx.f32 %0, %1;" : "=f"(y) : "f"(x)); return y;
}
static __device__ __forceinline__ float sigt(float x) {
    return fmaf(tanha(0.5f * x), 0.5f, 0.5f);
}
#define MMAB(c, a, b) asm volatile( \
    "mma.sync.aligned.m16n8k16.row.col.f32.bf16.bf16.f32 " \
    "{%0,%1,%2,%3},{%4,%5,%6,%7},{%8,%9},{%0,%1,%2,%3};" \
    : "+f"((c)[0]), "+f"((c)[1]), "+f"((c)[2]), "+f"((c)[3]) \
    : "r"((a).x), "r"((a).y), "r"((a).z), "r"((a).w), "r"((b).x), "r"((b).y))
#define GROUP_BAR(mg) asm volatile("bar.sync %0, %1;" :: "r"(1 + (mg)), "r"(128) : "memory")

// One GRU layer, 24 steps, free-running 128-thread mg-groups (cross-SMSP).
// NEW vs R16: hh B-frags hoisted to registers (t-invariant); voxel-halves (mi)
// processed sequentially to halve C-frag registers; sel slices stored directly.
template<bool L0, bool LAST>
static __device__ void layer_run(float* __restrict__ sm, int tid, int blk,
                                 int whO, int wiO, int bsO, int t1, int t2)
{
    const int lane = tid & 31, w = tid >> 5;
    const int mg = w >> 2, ng = w & 3;           // cross-SMSP groups (R16 fix)
    const int gq = lane >> 2, cc = lane & 3;
    const int vbase = blk * VB;
    const uint2* WHu = (const uint2*)(sm + whO);
    const uint2* WIu = (const uint2*)(sm + wiO);
    const float* BS = sm + bsO;

    // hoist hh weight B-frags: [ji][type][kt2], 24 uint2 = 48 regs
    uint2 whreg[24];
    #pragma unroll
    for (int ji = 0; ji < 2; ++ji)
        #pragma unroll
        for (int ty = 0; ty < 3; ++ty)
            #pragma unroll
            for (int kt2 = 0; kt2 < 4; ++kt2)
                whreg[(ji * 3 + ty) * 4 + kt2] =
                    WHu[((ty * 8 + 2 * ng + ji) * 4 + kt2) * 32 + lane];

    float hp[16];
    #pragma unroll
    for (int i = 0; i < 16; ++i) hp[i] = 0.f;

    for (int t = 0; t < TS; ++t) {
        uint4*       hb_n = (uint4*)(sm + ((t & 1) ? S_H0 : S_H1));
        const uint4* hb_c = (const uint4*)(sm + ((t & 1) ? S_H1 : S_H0));

        #pragma unroll
        for (int mi = 0; mi < 2; ++mi) {
            const int mt = 2 * mg + mi;
            float cr[2][4], cz[2][4], cnh[2][4], cnx[2][4];
            #pragma unroll
            for (int ji = 0; ji < 2; ++ji)
                #pragma unroll
                for (int q = 0; q < 4; ++q) {
                    cr[ji][q] = 0.f; cz[ji][q] = 0.f;
                    cnh[ji][q] = 0.f; cnx[ji][q] = 0.f;
                }

            // ih MMAs (weights from smem; x from global/L2)
            if (!L0) {
                const uint4* xs = &g_actb[(size_t)(t * 128 + blk) * 1024];
                #pragma unroll
                for (int kt2 = 0; kt2 < 4; ++kt2) {
                    uint4 ax = xs[(mt * 4 + kt2) * 32 + lane];
                    #pragma unroll
                    for (int ji = 0; ji < 2; ++ji) {
                        int jt = 2 * ng + ji;
                        MMAB(cr[ji],  ax, WIu[((jt)      * 4 + kt2) * 32 + lane]);
                        MMAB(cz[ji],  ax, WIu[((8 + jt)  * 4 + kt2) * 32 + lane]);
                        MMAB(cnx[ji], ax, WIu[((16 + jt) * 4 + kt2) * 32 + lane]);
                    }
                }
            }
            // hh MMAs (weights from registers; skipped at t=0)
            if (t > 0) {
                #pragma unroll
                for (int kt2 = 0; kt2 < 4; ++kt2) {
                    uint4 ah = hb_c[(mt * 4 + kt2) * 32 + lane];
                    #pragma unroll
                    for (int ji = 0; ji < 2; ++ji) {
                        MMAB(cr[ji],  ah, whreg[(ji * 3 + 0) * 4 + kt2]);
                        MMAB(cz[ji],  ah, whreg[(ji * 3 + 1) * 4 + kt2]);
                        MMAB(cnh[ji], ah, whreg[(ji * 3 + 2) * 4 + kt2]);
                    }
                }
            }

            // thread-local combine for this voxel-half
            uint32_t rg[4];
            #pragma unroll
            for (int ji = 0; ji < 2; ++ji) {
                float hv[4];
                #pragma unroll
                for (int q = 0; q < 4; ++q) {
                    int j = 16 * ng + 8 * ji + 2 * cc + (q & 1);
                    int v = mt * 16 + gq + 8 * (q >> 1);
                    float xr = 0.f, xz = 0.f, xn;
                    if (L0) {
                        float xv = sm[S_VIN + t * VB + v];
                        xr = xv * sm[S_W0 + j];
                        xz = xv * sm[S_W0 + 64 + j];
                        xn = xv * sm[S_W0 + 128 + j] + BS[192 + j];
                    } else {
                        xn = cnx[ji][q] + BS[192 + j];
                    }
                    float r  = sigt(cr[ji][q] + xr + BS[j]);
                    float z  = sigt(cz[ji][q] + xz + BS[64 + j]);
                    float nn = tanha(xn + r * (cnh[ji][q] + BS[128 + j]));
                    int hi = (mi * 2 + ji) * 4 + q;
                    float hnv = (1.f - z) * nn + z * hp[hi];
                    hp[hi] = hnv;
                    hv[q] = hnv;
                    if (LAST) {
                        if (t == t2) g_sel2[(j << 14) + vbase + v] = hnv;
                        if (t == t1) g_sel1[(j << 14) + vbase + v] = hnv;
                    }
                }
                rg[ji * 2 + 0] = pkbf(hv[0], hv[1]);
                rg[ji * 2 + 1] = pkbf(hv[2], hv[3]);
            }
            uint4 u = make_uint4(rg[0], rg[1], rg[2], rg[3]);
            hb_n[(mt * 4 + ng) * 32 + lane] = u;
            if (!LAST)
                g_actb[(size_t)(t * 128 + blk) * 1024 + (mt * 4 + ng) * 32 + lane] = u;
        }
        GROUP_BAR(mg);   // only this 128-thread group converges
    }
}

__global__ void __launch_bounds__(NT)
fused_rnn_kernel(const float* __restrict__ x,   const int*   __restrict__ lengths,
                 const float* __restrict__ sf,  const float* __restrict__ bp,
                 const float* __restrict__ wih0,const float* __restrict__ whh0,
                 const float* __restrict__ bih0,const float* __restrict__ bhh0,
                 const float* __restrict__ wihL,const float* __restrict__ whhL,
                 const float* __restrict__ bihL,const float* __restrict__ bhhL,
                 const float* __restrict__ bng, const float* __restrict__ bnb,
                 const float* __restrict__ bnm, const float* __restrict__ bnv,
                 const float* __restrict__ fcW, const float* __restrict__ fcb,
                 const float* __restrict__ fcWo,const float* __restrict__ fcbo,
                 float* __restrict__ out)
{
    extern __shared__ float sm[];
    const int tid = threadIdx.x;
    const int blk = blockIdx.x;
    const int vbase = blk * VB;
    const int n  = vbase >> 12;
    const int sb = vbase & 4095;

    // ---- stage ALL layers' weights + biases up front ----
    for (int l = 0; l < 4; ++l) {
        const float* Wh = (l == 0) ? whh0 : whhL + (l - 1) * 12288;
        const float* Wi = (l == 0) ? wih0 : wihL + (l - 1) * 12288;
        const float* Bi = (l == 0) ? bih0 : bihL + (l - 1) * 192;
        const float* Bh = (l == 0) ? bhh0 : bhhL + (l - 1) * 192;
        int whO = (l == 0) ? 0 : (6144 + (l - 1) * 12288);
        uint32_t* WHu = (uint32_t*)(sm + whO);
        uint32_t* WIu = WHu + 6144;
        for (int idx = tid; idx < 6144; idx += NT) {
            int gt = idx >> 8, kt2 = (idx >> 6) & 3, ln = (idx >> 1) & 31, br = idx & 1;
            int g = gt * 8 + (ln >> 2);
            int k = kt2 * 16 + (ln & 3) * 2 + br * 8;
            WHu[idx] = pkbf(Wh[g * 64 + k], Wh[g * 64 + k + 1]);
            if (l > 0) WIu[idx] = pkbf(Wi[g * 64 + k], Wi[g * 64 + k + 1]);
        }
        if (tid < 64) {
            int j = tid;
            sm[S_BS + l * 256 + j]       = Bi[j] + Bh[j];
            sm[S_BS + l * 256 + 64 + j]  = Bi[64 + j] + Bh[64 + j];
            sm[S_BS + l * 256 + 128 + j] = Bh[128 + j];
            sm[S_BS + l * 256 + 192 + j] = Bi[128 + j];
        }
    }
    if (tid < 192) sm[S_W0 + tid] = wih0[tid];
    for (int idx = tid; idx < TS * VB; idx += NT) {   // vin[t][v]
        int t = idx >> 7, v = idx & 127;
        int p = t % 3;
        sm[S_VIN + idx] = x[n * 98304 + t * 4096 + sb + v] * sf[p] + bp[p];
    }
    __syncthreads();

    const int len = lengths[n];
    const int t1 = len - 1, t2 = len - 4;

    // ---- four layers, mg-groups free-running throughout ----
    layer_run<true , false>(sm, tid, blk, 0,     0,     S_BS,       t1, t2);
    layer_run<false, false>(sm, tid, blk, 6144,  12288, S_BS + 256, t1, t2);
    layer_run<false, false>(sm, tid, blk, 18432, 24576, S_BS + 512, t1, t2);
    layer_run<false, true >(sm, tid, blk, 30720, 36864, S_BS + 768, t1, t2);
    __syncthreads();

    // ---- head: sel = g_sel1 + g_sel2; 5x (BN+SiLU+FC); BN+SiLU; out ----
    float* A = sm + S_H0;    // [j][v] 64 x 128 (spans H0+H1)
    float* B = sm;           // first 8192 floats of (now dead) weight region
    float* WST = sm + 8192;  // per-iteration fcW staging (4096)
    #pragma unroll
    for (int it = 0; it < 16; ++it) {
        int idx = tid + it * NT, v = idx & 127, j = idx >> 7;
        A[j * VB + v] = g_sel1[(j << 14) + vbase + v] + g_sel2[(j << 14) + vbase + v];
    }
    __syncthreads();
    for (int i = 0; i < 5; ++i) {
        for (int idx = tid; idx < 4096; idx += NT) WST[idx] = fcW[i * 4096 + idx];
        #pragma unroll
        for (int it = 0; it < 16; ++it) {
            int idx = tid + it * NT, v = idx & 127, j = idx >> 7;
            float y = bng[i * 64 + j] * (A[j * VB + v] - bnm[i * 64 + j])
                      * rsqrtf(bnv[i * 64 + j] + 1e-5f) + bnb[i * 64 + j];
            A[j * VB + v] = y * sigt(y);
        }
        __syncthreads();
        #pragma unroll
        for (int it = 0; it < 16; ++it) {
            int idx = tid + it * NT, v = idx & 127, o = idx >> 7;
            float acc = fcb[i * 64 + o];
            #pragma unroll 8
            for (int j = 0; j < 64; ++j) acc += A[j * VB + v] * WST[o * 64 + j];
            B[o * VB + v] = acc;
        }
        __syncthreads();
        float* tswp = A; A = B; B = tswp;
    }
    #pragma unroll
    for (int it = 0; it < 16; ++it) {
        int idx = tid + it * NT, v = idx & 127, j = idx >> 7;
        float y = bng[5 * 64 + j] * (A[j * VB + v] - bnm[5 * 64 + j])
                  * rsqrtf(bnv[5 * 64 + j] + 1e-5f) + bnb[5 * 64 + j];
        A[j * VB + v] = y * sigt(y);
    }
    __syncthreads();
    if (tid < VB) {
        float acc = fcbo[0];
        #pragma unroll 8
        for (int j = 0; j < 64; ++j) acc += A[j * VB + tid] * fcWo[j];
        out[vbase + tid] = acc;
    }
}

extern "C" void kernel_launch(void* const* d_in, const int* in_sizes, int n_in,
                              void* d_out, int out_size)
{
    const float* x     = (const float*)d_in[0];
    const int*   lens  = (const int*)  d_in[1];
    const float* sf    = (const float*)d_in[2];
    const float* bp    = (const float*)d_in[3];
    const float* wih0  = (const float*)d_in[4];
    const float* whh0  = (const float*)d_in[5];
    const float* bih0  = (const float*)d_in[6];
    const float* bhh0  = (const float*)d_in[7];
    const float* wihL  = (const float*)d_in[8];
    const float* whhL  = (const float*)d_in[9];
    const float* bihL  = (const float*)d_in[10];
    const float* bhhL  = (const float*)d_in[11];
    const float* bng   = (const float*)d_in[12];
    const float* bnb   = (const float*)d_in[13];
    const float* bnm   = (const float*)d_in[14];
    const float* bnv   = (const float*)d_in[15];
    const float* fcW   = (const float*)d_in[16];
    const float* fcb   = (const float*)d_in[17];
    const float* fcWo  = (const float*)d_in[18];
    const float* fcbo  = (const float*)d_in[19];
    float* out = (float*)d_out;

    const size_t smem = SMEM_FLOATS * sizeof(float);   // 221,952 B
    cudaFuncSetAttribute(fused_rnn_kernel,
                         cudaFuncAttributeMaxDynamicSharedMemorySize, (int)smem);
    fused_rnn_kernel<<<128, NT, smem>>>(
        x, lens, sf, bp, wih0, whh0, bih0, bhh0,
        wihL, whhL, bihL, bhhL, bng, bnb, bnm, bnv,
        fcW, fcb, fcWo, fcbo, out);
}